// round 1
// baseline (speedup 1.0000x reference)
#include <cuda_runtime.h>
#include <cstdint>

#define N_NODES 100000
#define N_PAIRS 640000
#define F_TOTAL 128
#define N_HEADS 8
#define HEAD_DIM 16

// Scratch for projected q, k, v in (node, head*16+e) layout (same as output).
__device__ float g_q[N_NODES * F_TOTAL];
__device__ float g_k[N_NODES * F_TOTAL];
__device__ float g_v[N_NODES * F_TOTAL];

// Padded per-head stride in shared: 260 floats -> h*260 % 32 = h*4, so the 8
// per-head float4 broadcasts hit disjoint bank quads (conflict-free).
#define W_STRIDE 260

__global__ void __launch_bounds__(256) proj_kernel(
    const float* __restrict__ x,
    const float* __restrict__ wq,
    const float* __restrict__ wk,
    const float* __restrict__ wv)
{
    __shared__ float sq[N_HEADS * W_STRIDE];
    __shared__ float sk[N_HEADS * W_STRIDE];
    __shared__ float sv[N_HEADS * W_STRIDE];

    // Stage weights (2048 floats each) into padded shared.
    for (int i = threadIdx.x; i < N_HEADS * HEAD_DIM * HEAD_DIM; i += 256) {
        int h = i >> 8;          // /256
        int r = i & 255;
        sq[h * W_STRIDE + r] = wq[i];
        sk[h * W_STRIDE + r] = wk[i];
        sv[h * W_STRIDE + r] = wv[i];
    }
    __syncthreads();

    int gid = blockIdx.x * 256 + threadIdx.x;   // gid = node*8 + head
    if (gid >= N_NODES * N_HEADS) return;
    int n = gid >> 3;
    int h = gid & 7;

    // Load this (node, head) 16-float slice of x.
    const float4* xp = reinterpret_cast<const float4*>(x + (size_t)n * F_TOTAL + h * HEAD_DIM);
    float4 xv0 = xp[0], xv1 = xp[1], xv2 = xp[2], xv3 = xp[3];
    float xr[16] = {xv0.x, xv0.y, xv0.z, xv0.w,
                    xv1.x, xv1.y, xv1.z, xv1.w,
                    xv2.x, xv2.y, xv2.z, xv2.w,
                    xv3.x, xv3.y, xv3.z, xv3.w};

    const float4* wq4 = reinterpret_cast<const float4*>(sq + h * W_STRIDE);
    const float4* wk4 = reinterpret_cast<const float4*>(sk + h * W_STRIDE);
    const float4* wv4 = reinterpret_cast<const float4*>(sv + h * W_STRIDE);

    float qo[16], ko[16], vo[16];
#pragma unroll
    for (int e = 0; e < 16; e++) {
        float aq = 0.f, ak = 0.f, av = 0.f;
#pragma unroll
        for (int d4 = 0; d4 < 4; d4++) {
            float4 a = wq4[e * 4 + d4];
            float4 b = wk4[e * 4 + d4];
            float4 c = wv4[e * 4 + d4];
            float x0 = xr[4 * d4 + 0], x1 = xr[4 * d4 + 1];
            float x2 = xr[4 * d4 + 2], x3 = xr[4 * d4 + 3];
            aq += x0 * a.x + x1 * a.y + x2 * a.z + x3 * a.w;
            ak += x0 * b.x + x1 * b.y + x2 * b.z + x3 * b.w;
            av += x0 * c.x + x1 * c.y + x2 * c.z + x3 * c.w;
        }
        qo[e] = aq; ko[e] = ak; vo[e] = av;
    }

    size_t base = (size_t)n * F_TOTAL + h * HEAD_DIM;
    float4* qdst = reinterpret_cast<float4*>(g_q + base);
    float4* kdst = reinterpret_cast<float4*>(g_k + base);
    float4* vdst = reinterpret_cast<float4*>(g_v + base);
#pragma unroll
    for (int i = 0; i < 4; i++) {
        qdst[i] = make_float4(qo[4*i], qo[4*i+1], qo[4*i+2], qo[4*i+3]);
        kdst[i] = make_float4(ko[4*i], ko[4*i+1], ko[4*i+2], ko[4*i+3]);
        vdst[i] = make_float4(vo[4*i], vo[4*i+1], vo[4*i+2], vo[4*i+3]);
    }
}

__global__ void __launch_bounds__(256) zero_kernel(float4* __restrict__ out, int n4)
{
    int i = blockIdx.x * 256 + threadIdx.x;
    if (i < n4) out[i] = make_float4(0.f, 0.f, 0.f, 0.f);
}

// One warp per pair. Lane l owns features [4l, 4l+4); head = l/4.
__global__ void __launch_bounds__(256) pair_kernel(
    const float* __restrict__ w_ij,
    const int*   __restrict__ idx_i,
    const int*   __restrict__ idx_j,
    const float* __restrict__ phi,
    float*       __restrict__ out)
{
    int p = blockIdx.x * 8 + (threadIdx.x >> 5);
    if (p >= N_PAIRS) return;
    int lane = threadIdx.x & 31;

    int i = idx_i[p];
    int j = idx_j[p];
    float ph = phi[p];

    const float4 w = reinterpret_cast<const float4*>(w_ij)[(size_t)p * 32 + lane];
    const float4 q = reinterpret_cast<const float4*>(g_q)[(size_t)i * 32 + lane];
    const float4 k = reinterpret_cast<const float4*>(g_k)[(size_t)j * 32 + lane];
    const float4 v = reinterpret_cast<const float4*>(g_v)[(size_t)j * 32 + lane];

    float part = q.x * w.x * k.x + q.y * w.y * k.y
               + q.z * w.z * k.z + q.w * w.w * k.w;
    // reduce over the 4 lanes of this head
    part += __shfl_xor_sync(0xFFFFFFFFu, part, 1);
    part += __shfl_xor_sync(0xFFFFFFFFu, part, 2);

    float alpha = part * 0.25f * ph;   // 1/sqrt(16) = 0.25

    float m0 = alpha * v.x, m1 = alpha * v.y, m2 = alpha * v.z, m3 = alpha * v.w;
    float* dst = out + (size_t)i * F_TOTAL + lane * 4;
    asm volatile("red.global.add.v4.f32 [%0], {%1, %2, %3, %4};"
                 :: "l"(dst), "f"(m0), "f"(m1), "f"(m2), "f"(m3)
                 : "memory");
}

extern "C" void kernel_launch(void* const* d_in, const int* in_sizes, int n_in,
                              void* d_out, int out_size)
{
    const float* x      = (const float*)d_in[0];
    const float* w_ij   = (const float*)d_in[1];
    const int*   idx_i  = (const int*)  d_in[2];
    const int*   idx_j  = (const int*)  d_in[3];
    const float* phi    = (const float*)d_in[4];
    const float* wq     = (const float*)d_in[5];
    const float* wk     = (const float*)d_in[6];
    const float* wv     = (const float*)d_in[7];
    float* out = (float*)d_out;

    // Zero output (poisoned by harness; we scatter-add into it).
    int n4 = out_size / 4;
    zero_kernel<<<(n4 + 255) / 256, 256>>>(reinterpret_cast<float4*>(out), n4);

    // q/k/v projections
    int total = N_NODES * N_HEADS;
    proj_kernel<<<(total + 255) / 256, 256>>>(x, wq, wk, wv);

    // pair phase: one warp per pair
    pair_kernel<<<(N_PAIRS + 7) / 8, 256>>>(w_ij, idx_i, idx_j, phi, out);
}